// round 6
// baseline (speedup 1.0000x reference)
#include <cuda_runtime.h>
#include <cuda_fp16.h>
#include <math_constants.h>

// Tropical (max-plus) depthwise 5x5 conv, stride=1, pad=2, dil=1.
// x: [8,32,224,224] f32; kernel: [32,1,5,5] f32; out: f32 same shape.
// fp16x2 core (HADD2 on fma-pipe + HMNMX2 on alu-pipe), tree maxes,
// fully-unrolled row stream (ptxas batches the LDGs itself — R5 showed
// manual pipelining hurts). R6: 7 CTAs/SM (49 warps) at unchanged 40 regs.

#define TC_H 224
#define TC_W 224
#define TC_C 32
#define TC_TY 8   // output rows per thread

__global__ __launch_bounds__(224, 7)
void tropical_conv_h2_kernel(const float* __restrict__ x,
                             const float* __restrict__ ker,
                             float* __restrict__ out)
{
    const int tid = threadIdx.x;           // 0..223 (7 full warps, no dead lanes)
    const int tx  = tid % 56;              // column lane
    const int sub = tid / 56;              // row subtile 0..3
    const int x0  = tx * 4;                // output column base (0..220)
    const int plane = blockIdx.y;          // b*32 + c
    const int c = plane & (TC_C - 1);
    const int y0 = (blockIdx.x * 4 + sub) * TC_TY;

    const float* __restrict__ xp = x + (size_t)plane * (TC_H * TC_W);
    float* __restrict__ op = out + (size_t)plane * (TC_H * TC_W);

    // Weights as broadcast half2.
    half2 w2[5][5];
    const float* kc = ker + c * 25;
#pragma unroll
    for (int i = 0; i < 5; i++)
#pragma unroll
        for (int j = 0; j < 5; j++)
            w2[i][j] = __float2half2_rn(__ldg(kc + i * 5 + j));

    const float NEGF = -CUDART_INF_F;
    const half2 NEG2 = __float2half2_rn(NEGF);

    half2 acc[TC_TY][2];
#pragma unroll
    for (int yy = 0; yy < TC_TY; yy++) {
        acc[yy][0] = NEG2;
        acc[yy][1] = NEG2;
    }

    // Stream input rows r = y0-2 .. y0+TY+1 (fully unrolled).
#pragma unroll
    for (int rr = 0; rr < TC_TY + 4; rr++) {
        const int r = y0 - 2 + rr;
        float f0, f1, f2, f3, f4, f5, f6, f7;     // input cols x0-2 .. x0+5
        if ((unsigned)r < (unsigned)TC_H) {
            const float* row = xp + r * TC_W;
            float4 m = *reinterpret_cast<const float4*>(row + x0);
            f2 = m.x; f3 = m.y; f4 = m.z; f5 = m.w;
            if (x0 > 0) {
                float2 l = *reinterpret_cast<const float2*>(row + x0 - 2);
                f0 = l.x; f1 = l.y;
            } else { f0 = NEGF; f1 = NEGF; }
            if (x0 < TC_W - 4) {
                float2 rg = *reinterpret_cast<const float2*>(row + x0 + 4);
                f6 = rg.x; f7 = rg.y;
            } else { f6 = NEGF; f7 = NEGF; }
        } else {
            f0 = f1 = f2 = f3 = f4 = f5 = f6 = f7 = NEGF;
        }

        // Pack: v0=(c-2,c-1) v1=(c0,c1) v2=(c2,c3) v3=(c4,c5); shifted via F2FP.
        half2 v0  = __floats2half2_rn(f0, f1);
        half2 v1  = __floats2half2_rn(f2, f3);
        half2 v2  = __floats2half2_rn(f4, f5);
        half2 v3  = __floats2half2_rn(f6, f7);
        half2 s01 = __floats2half2_rn(f1, f2);   // (c-1,c0)
        half2 s12 = __floats2half2_rn(f3, f4);   // (c1,c2)
        half2 s23 = __floats2half2_rn(f5, f6);   // (c3,c4)

#pragma unroll
        for (int yy = 0; yy < TC_TY; yy++) {
            const int ki = yy - rr + 4;    // compile-time after unroll
            if (ki < 0 || ki > 4) continue;
            // acc0 covers (c0,c1): windows v0,s01,v1,s12,v2 with kj=4..0
            {
                half2 c0 = __hadd2(v0,  w2[ki][4]);
                half2 c1 = __hadd2(s01, w2[ki][3]);
                half2 c2 = __hadd2(v1,  w2[ki][2]);
                half2 c3 = __hadd2(s12, w2[ki][1]);
                half2 c4 = __hadd2(v2,  w2[ki][0]);
                half2 t0 = __hmax2(c0, c1);
                half2 t1 = __hmax2(c2, c3);
                half2 t2 = __hmax2(t0, t1);
                half2 t3 = __hmax2(t2, c4);
                acc[yy][0] = __hmax2(acc[yy][0], t3);
            }
            // acc1 covers (c2,c3): windows v1,s12,v2,s23,v3
            {
                half2 c0 = __hadd2(v1,  w2[ki][4]);
                half2 c1 = __hadd2(s12, w2[ki][3]);
                half2 c2 = __hadd2(v2,  w2[ki][2]);
                half2 c3 = __hadd2(s23, w2[ki][1]);
                half2 c4 = __hadd2(v3,  w2[ki][0]);
                half2 t0 = __hmax2(c0, c1);
                half2 t1 = __hmax2(c2, c3);
                half2 t2 = __hmax2(t0, t1);
                half2 t3 = __hmax2(t2, c4);
                acc[yy][1] = __hmax2(acc[yy][1], t3);
            }
        }
    }

#pragma unroll
    for (int yy = 0; yy < TC_TY; yy++) {
        const int y = y0 + yy;
        float2 lo = __half22float2(acc[yy][0]);
        float2 hi = __half22float2(acc[yy][1]);
        float4 o; o.x = lo.x; o.y = lo.y; o.z = hi.x; o.w = hi.y;
        *reinterpret_cast<float4*>(op + y * TC_W + x0) = o;
    }
}

extern "C" void kernel_launch(void* const* d_in, const int* in_sizes, int n_in,
                              void* d_out, int out_size)
{
    const float* x = (const float*)d_in[0];     // [8,32,224,224]
    const float* k = (const float*)d_in[1];     // [32,1,5,5]
    float* out = (float*)d_out;

    dim3 block(224, 1, 1);
    dim3 grid(7, 256, 1);                       // 7*4*8 = 224 rows; 256 planes
    tropical_conv_h2_kernel<<<grid, block>>>(x, k, out);
}

// round 7
// speedup vs baseline: 1.4084x; 1.4084x over previous
#include <cuda_runtime.h>
#include <cuda_fp16.h>
#include <math_constants.h>

// Tropical (max-plus) depthwise 5x5 conv, stride=1, pad=2, dil=1.
// x: [8,32,224,224] f32; kernel: [32,1,5,5] f32; out: f32 same shape.
// fp16x2 core (HADD2+HMNMX2, tree maxes). R7: 8-wide x 4-tall thread tile
// (was 4x8) — halves loads and packs per output; core op count unchanged.

#define TC_H 224
#define TC_W 224
#define TC_C 32
#define TC_TY 4    // output rows per thread
                   // output cols per thread = 8

__global__ __launch_bounds__(224, 5)
void tropical_conv_h2_kernel(const float* __restrict__ x,
                             const float* __restrict__ ker,
                             float* __restrict__ out)
{
    const int tid = threadIdx.x;           // 0..223 (7 full warps)
    const int tx  = tid % 28;              // column lane: 28*8 = 224 cols
    const int sub = tid / 28;              // row subtile 0..7
    const int x0  = tx * 8;                // output column base (0..216)
    const int plane = blockIdx.y;          // b*32 + c
    const int c = plane & (TC_C - 1);
    const int y0 = (blockIdx.x * 8 + sub) * TC_TY;   // 7*8*4 = 224 rows

    const float* __restrict__ xp = x + (size_t)plane * (TC_H * TC_W);
    float* __restrict__ op = out + (size_t)plane * (TC_H * TC_W);

    // Weights as broadcast half2.
    half2 w2[5][5];
    const float* kc = ker + c * 25;
#pragma unroll
    for (int i = 0; i < 5; i++)
#pragma unroll
        for (int j = 0; j < 5; j++)
            w2[i][j] = __float2half2_rn(__ldg(kc + i * 5 + j));

    const float NEGF = -CUDART_INF_F;
    const half2 NEG2 = __float2half2_rn(NEGF);

    half2 acc[TC_TY][4];                   // 4 half2 = 8 output cols per row
#pragma unroll
    for (int yy = 0; yy < TC_TY; yy++)
#pragma unroll
        for (int a = 0; a < 4; a++)
            acc[yy][a] = NEG2;

    // Stream input rows r = y0-2 .. y0+TY+1 (fully unrolled; ptxas batches LDGs).
#pragma unroll
    for (int rr = 0; rr < TC_TY + 4; rr++) {
        const int r = y0 - 2 + rr;
        float f0, f1, f2, f3, f4, f5, f6, f7, f8, f9, f10, f11; // cols x0-2..x0+9
        if ((unsigned)r < (unsigned)TC_H) {
            const float* row = xp + r * TC_W;
            float4 m0 = *reinterpret_cast<const float4*>(row + x0);
            float4 m1 = *reinterpret_cast<const float4*>(row + x0 + 4);
            f2 = m0.x; f3 = m0.y; f4 = m0.z; f5 = m0.w;
            f6 = m1.x; f7 = m1.y; f8 = m1.z; f9 = m1.w;
            if (x0 > 0) {
                float2 l = *reinterpret_cast<const float2*>(row + x0 - 2);
                f0 = l.x; f1 = l.y;
            } else { f0 = NEGF; f1 = NEGF; }
            if (x0 < TC_W - 8) {
                float2 rg = *reinterpret_cast<const float2*>(row + x0 + 8);
                f10 = rg.x; f11 = rg.y;
            } else { f10 = NEGF; f11 = NEGF; }
        } else {
            f0 = f1 = f2 = f3 = f4 = f5 = NEGF;
            f6 = f7 = f8 = f9 = f10 = f11 = NEGF;
        }

        // Aligned pairs v0..v5 and shifted pairs s01..s45 (F2FP, fma pipe).
        half2 v0  = __floats2half2_rn(f0,  f1);   // (c-2,c-1)
        half2 v1  = __floats2half2_rn(f2,  f3);   // (c0,c1)
        half2 v2  = __floats2half2_rn(f4,  f5);   // (c2,c3)
        half2 v3  = __floats2half2_rn(f6,  f7);   // (c4,c5)
        half2 v4  = __floats2half2_rn(f8,  f9);   // (c6,c7)
        half2 v5  = __floats2half2_rn(f10, f11);  // (c8,c9)
        half2 s01 = __floats2half2_rn(f1,  f2);   // (c-1,c0)
        half2 s12 = __floats2half2_rn(f3,  f4);   // (c1,c2)
        half2 s23 = __floats2half2_rn(f5,  f6);   // (c3,c4)
        half2 s34 = __floats2half2_rn(f7,  f8);   // (c5,c6)
        half2 s45 = __floats2half2_rn(f9,  f10);  // (c7,c8)

        // Window sets per acc k (cols 2k,2k+1), kj = 4..0:
        half2 W0[4] = { v0,  v1,  v2,  v3  };
        half2 W1[4] = { s01, s12, s23, s34 };
        half2 W2[4] = { v1,  v2,  v3,  v4  };
        half2 W3[4] = { s12, s23, s34, s45 };
        half2 W4[4] = { v2,  v3,  v4,  v5  };

#pragma unroll
        for (int yy = 0; yy < TC_TY; yy++) {
            const int ki = yy - rr + 4;    // compile-time after unroll
            if (ki < 0 || ki > 4) continue;
#pragma unroll
            for (int a = 0; a < 4; a++) {
                half2 c0 = __hadd2(W0[a], w2[ki][4]);
                half2 c1 = __hadd2(W1[a], w2[ki][3]);
                half2 c2 = __hadd2(W2[a], w2[ki][2]);
                half2 c3 = __hadd2(W3[a], w2[ki][1]);
                half2 c4 = __hadd2(W4[a], w2[ki][0]);
                half2 t0 = __hmax2(c0, c1);
                half2 t1 = __hmax2(c2, c3);
                half2 t2 = __hmax2(t0, t1);
                half2 t3 = __hmax2(t2, c4);
                acc[yy][a] = __hmax2(acc[yy][a], t3);
            }
        }
    }

#pragma unroll
    for (int yy = 0; yy < TC_TY; yy++) {
        const int y = y0 + yy;
        float2 p0 = __half22float2(acc[yy][0]);
        float2 p1 = __half22float2(acc[yy][1]);
        float2 p2 = __half22float2(acc[yy][2]);
        float2 p3 = __half22float2(acc[yy][3]);
        float4 o0; o0.x = p0.x; o0.y = p0.y; o0.z = p1.x; o0.w = p1.y;
        float4 o1; o1.x = p2.x; o1.y = p2.y; o1.z = p3.x; o1.w = p3.y;
        *reinterpret_cast<float4*>(op + y * TC_W + x0)     = o0;
        *reinterpret_cast<float4*>(op + y * TC_W + x0 + 4) = o1;
    }
}

extern "C" void kernel_launch(void* const* d_in, const int* in_sizes, int n_in,
                              void* d_out, int out_size)
{
    const float* x = (const float*)d_in[0];     // [8,32,224,224]
    const float* k = (const float*)d_in[1];     // [32,1,5,5]
    float* out = (float*)d_out;

    dim3 block(224, 1, 1);
    dim3 grid(7, 256, 1);                       // 7 * 8 * 4 = 224 rows; 256 planes
    tropical_conv_h2_kernel<<<grid, block>>>(x, k, out);
}